// round 2
// baseline (speedup 1.0000x reference)
#include <cuda_runtime.h>
#include <cstdint>
#include <cstddef>

#define B_  16
#define N_  192
#define H_  128
#define F_  128
#define G_  50
#define BN_ (B_*N_)

// scratch for nf = features @ W_f + b_f   [B, N, F]
__device__ float g_nf[BN_ * F_];

__device__ __forceinline__ float softplus_f(float x) {
    // stable softplus; __expf/__logf accurate to ~1e-6 rel here (arg of log in (1,2])
    return fmaxf(x, 0.f) + __logf(1.f + __expf(-fabsf(x)));
}

// ---------------------------------------------------------------------------
// Kernel A: nf[b,j,f] = features[b,j,:] @ W_f[:,f] + b_f[f]
// ---------------------------------------------------------------------------
__global__ void nf_kernel(const float* __restrict__ features,
                          const float* __restrict__ Wf,
                          const float* __restrict__ bf) {
    int bj = blockIdx.x;       // 0..BN-1
    int f  = threadIdx.x;      // 0..127
    const float* ft = features + (size_t)bj * H_;
    float a0 = bf[f], a1 = 0.f;
#pragma unroll
    for (int h = 0; h < H_; h += 2) {
        a0 = fmaf(ft[h],     Wf[(h)     * F_ + f], a0);
        a1 = fmaf(ft[h + 1], Wf[(h + 1) * F_ + f], a1);
    }
    g_nf[(size_t)bj * F_ + f] = a0 + a1;
}

// ---------------------------------------------------------------------------
// Main fused kernel: one CTA per (b,i)
// ---------------------------------------------------------------------------
struct __align__(16) Smem {
    float Hs[N_ * F_];                                  // 98304 B  softplus(rbf@W1+b1)
    float W1[G_ * F_];                                  // 25600 B
    union { float rbf[N_ * 52]; float W2[F_ * F_]; } u; // 65536 B (rbf staged, then W2)
    float b1[F_];
    float b2[F_];
    float agg[4][F_];
    float o1[F_];
    int   jlist[208];
    int   cnt;
};

__global__ __launch_bounds__(512, 1)
void main_kernel(const float* __restrict__ rbf,
                 const int*   __restrict__ mask,
                 const float* __restrict__ features,
                 const float* __restrict__ W1g, const float* __restrict__ b1g,
                 const float* __restrict__ W2g, const float* __restrict__ b2g,
                 const float* __restrict__ Wo1, const float* __restrict__ bo1,
                 const float* __restrict__ Wo2, const float* __restrict__ bo2,
                 float* __restrict__ out) {
    extern __shared__ char smem_raw[];
    Smem& S = *reinterpret_cast<Smem*>(smem_raw);
    const int tid = threadIdx.x;
    const int bi  = blockIdx.x;        // b*N + i
    const int b   = bi / N_;

    // ---- phase 0: stage W1, biases, rbf tile (padded rows of 52 for float4) ----
    if (tid == 0) S.cnt = 0;
    for (int idx = tid; idx < G_ * F_; idx += 512) S.W1[idx] = W1g[idx];
    if (tid < F_) { S.b1[tid] = b1g[tid]; S.b2[tid] = b2g[tid]; }
    {
        const float* rtile = rbf + (size_t)bi * (N_ * G_);
        for (int idx = tid; idx < N_ * G_; idx += 512) {
            int j = idx / G_, g = idx - j * G_;
            S.u.rbf[j * 52 + g] = rtile[idx];
        }
    }
    __syncthreads();

    // ---- mask compaction (order-free) overlapped with GEMM1 ----
    if (tid < N_) {
        if (mask[(size_t)bi * N_ + tid]) {
            int pos = atomicAdd(&S.cnt, 1);
            S.jlist[pos] = tid;
        }
    }

    // ---- GEMM1: Hs[j,k] = softplus(rbf[j,:] @ W1[:,k] + b1[k]) ----
    {
        const int k  = tid & 127;
        const int jg = tid >> 7;                 // 0..3, 48 j's each
        for (int j = jg * 48; j < jg * 48 + 48; ++j) {
            const float* r = &S.u.rbf[j * 52];
            float a0 = S.b1[k], a1 = 0.f;
#pragma unroll
            for (int g = 0; g < 48; g += 4) {
                float4 r4 = *reinterpret_cast<const float4*>(r + g);
                a0 = fmaf(r4.x, S.W1[(g    ) * F_ + k], a0);
                a1 = fmaf(r4.y, S.W1[(g + 1) * F_ + k], a1);
                a0 = fmaf(r4.z, S.W1[(g + 2) * F_ + k], a0);
                a1 = fmaf(r4.w, S.W1[(g + 3) * F_ + k], a1);
            }
            a0 = fmaf(r[48], S.W1[48 * F_ + k], a0);
            a1 = fmaf(r[49], S.W1[49 * F_ + k], a1);
            S.Hs[j * F_ + k] = softplus_f(a0 + a1);
        }
    }
    __syncthreads();

    // ---- stage W2 (overwrites rbf region); pad active list to multiple of 8 ----
    for (int idx = tid; idx < (F_ * F_) / 4; idx += 512) {
        reinterpret_cast<float4*>(S.u.W2)[idx] =
            reinterpret_cast<const float4*>(W2g)[idx];
    }
    if (tid == 0) {
        int c = S.cnt;
        while (c & 7) S.jlist[c++] = 255;   // sentinel
        S.cnt = c;
    }
    __syncthreads();

    // ---- GEMM2 + masked weighted reduction over active j ----
    {
        const int f    = tid & 127;
        const int grp  = tid >> 7;
        const int cntp = S.cnt;
        float acc = 0.f;
        for (int p = grp * 2; p < cntp; p += 8) {
            int ja = S.jlist[p], jb = S.jlist[p + 1];
            bool va = ja < N_, vb = jb < N_;
            float wa = va ? g_nf[((size_t)b * N_ + ja) * F_ + f] : 0.f;
            float wb = vb ? g_nf[((size_t)b * N_ + jb) * F_ + f] : 0.f;
            int ja2 = va ? ja : 0, jb2 = vb ? jb : 0;
            const float* Ha = &S.Hs[ja2 * F_];
            const float* Hb = &S.Hs[jb2 * F_];
            float fa0 = S.b2[f], fa1 = 0.f, fb0 = S.b2[f], fb1 = 0.f;
#pragma unroll
            for (int k = 0; k < F_; k += 4) {
                float4 ha = *reinterpret_cast<const float4*>(Ha + k);
                float4 hb = *reinterpret_cast<const float4*>(Hb + k);
                float w0 = S.u.W2[(k    ) * F_ + f];
                float w1 = S.u.W2[(k + 1) * F_ + f];
                float w2 = S.u.W2[(k + 2) * F_ + f];
                float w3 = S.u.W2[(k + 3) * F_ + f];
                fa0 = fmaf(ha.x, w0, fa0);  fa1 = fmaf(ha.y, w1, fa1);
                fa0 = fmaf(ha.z, w2, fa0);  fa1 = fmaf(ha.w, w3, fa1);
                fb0 = fmaf(hb.x, w0, fb0);  fb1 = fmaf(hb.y, w1, fb1);
                fb0 = fmaf(hb.z, w2, fb0);  fb1 = fmaf(hb.w, w3, fb1);
            }
            acc = fmaf(wa, fa0 + fa1, acc);
            acc = fmaf(wb, fb0 + fb1, acc);
        }
        S.agg[grp][f] = acc;
    }
    __syncthreads();

    // ---- dense_out: out = features + softplus(agg@Wo1+bo1)@Wo2 + bo2 ----
    if (tid < F_) {
        float a = S.agg[0][tid] + S.agg[1][tid] + S.agg[2][tid] + S.agg[3][tid];
        S.agg[0][tid] = a;
    }
    __syncthreads();
    if (tid < H_) {
        const int h = tid;
        float a0 = bo1[h], a1 = 0.f;
#pragma unroll 8
        for (int f2 = 0; f2 < F_; f2 += 2) {
            a0 = fmaf(S.agg[0][f2],     Wo1[(f2)     * H_ + h], a0);
            a1 = fmaf(S.agg[0][f2 + 1], Wo1[(f2 + 1) * H_ + h], a1);
        }
        S.o1[h] = softplus_f(a0 + a1);
    }
    __syncthreads();
    if (tid < H_) {
        const int h = tid;
        float a0 = bo2[h] + features[(size_t)bi * H_ + h], a1 = 0.f;
#pragma unroll 8
        for (int hp = 0; hp < H_; hp += 2) {
            a0 = fmaf(S.o1[hp],     Wo2[(hp)     * H_ + h], a0);
            a1 = fmaf(S.o1[hp + 1], Wo2[(hp + 1) * H_ + h], a1);
        }
        out[(size_t)bi * H_ + h] = a0 + a1;
    }
}

// ---------------------------------------------------------------------------
extern "C" void kernel_launch(void* const* d_in, const int* in_sizes, int n_in,
                              void* d_out, int out_size) {
    const float* features = (const float*)d_in[0];
    const float* rbf      = (const float*)d_in[1];
    const int*   mask     = (const int*)  d_in[2];
    const float* W_rbf1   = (const float*)d_in[3];
    const float* b_rbf1   = (const float*)d_in[4];
    const float* W_rbf2   = (const float*)d_in[5];
    const float* b_rbf2   = (const float*)d_in[6];
    const float* W_f      = (const float*)d_in[7];
    const float* b_f      = (const float*)d_in[8];
    const float* W_o1     = (const float*)d_in[9];
    const float* b_o1     = (const float*)d_in[10];
    const float* W_o2     = (const float*)d_in[11];
    const float* b_o2     = (const float*)d_in[12];
    float* out = (float*)d_out;

    cudaFuncSetAttribute(main_kernel,
                         cudaFuncAttributeMaxDynamicSharedMemorySize,
                         (int)sizeof(Smem));

    nf_kernel<<<BN_, 128>>>(features, W_f, b_f);
    main_kernel<<<BN_, 512, sizeof(Smem)>>>(rbf, mask, features,
                                            W_rbf1, b_rbf1, W_rbf2, b_rbf2,
                                            W_o1, b_o1, W_o2, b_o2, out);
}

// round 4
// speedup vs baseline: 3.5504x; 3.5504x over previous
#include <cuda_runtime.h>
#include <cuda_fp16.h>
#include <cstdint>
#include <cstddef>

#define B_  16
#define N_  192
#define H_  128
#define F_  128
#define G_  50
#define BN_ (B_*N_)

#define PA  72    // A (rbf) pitch in halves
#define PB  136   // W1/W2/Hs pitch in halves

// ---------------- global scratch ----------------
__device__ float g_nf[BN_ * F_];   // nf = features@W_f + b_f

__device__ __forceinline__ float softplus_f(float x) {
    return fmaxf(x, 0.f) + __logf(1.f + __expf(-fabsf(x)));
}

__device__ __forceinline__ uint32_t smem_u32(const void* p) {
    uint32_t a;
    asm("{ .reg .u64 t; cvta.to.shared.u64 t, %1; cvt.u32.u64 %0, t; }" : "=r"(a) : "l"(p));
    return a;
}

__device__ __forceinline__ void ldsm_x4(uint32_t addr, uint32_t& r0, uint32_t& r1,
                                        uint32_t& r2, uint32_t& r3) {
    asm volatile("ldmatrix.sync.aligned.m8n8.x4.shared.b16 {%0,%1,%2,%3}, [%4];"
                 : "=r"(r0), "=r"(r1), "=r"(r2), "=r"(r3) : "r"(addr));
}
__device__ __forceinline__ void ldsm_x4_t(uint32_t addr, uint32_t& r0, uint32_t& r1,
                                          uint32_t& r2, uint32_t& r3) {
    asm volatile("ldmatrix.sync.aligned.m8n8.x4.trans.shared.b16 {%0,%1,%2,%3}, [%4];"
                 : "=r"(r0), "=r"(r1), "=r"(r2), "=r"(r3) : "r"(addr));
}
__device__ __forceinline__ void mma16816(float* c, uint32_t a0, uint32_t a1,
                                         uint32_t a2, uint32_t a3,
                                         uint32_t b0, uint32_t b1) {
    asm volatile(
        "mma.sync.aligned.m16n8k16.row.col.f32.f16.f16.f32 "
        "{%0,%1,%2,%3}, {%4,%5,%6,%7}, {%8,%9}, {%0,%1,%2,%3};"
        : "+f"(c[0]), "+f"(c[1]), "+f"(c[2]), "+f"(c[3])
        : "r"(a0), "r"(a1), "r"(a2), "r"(a3), "r"(b0), "r"(b1));
}

// ---------------- prep kernel ----------------
__global__ void nf_kernel(const float* __restrict__ features,
                          const float* __restrict__ Wf,
                          const float* __restrict__ bf) {
    int bj = blockIdx.x;
    int f  = threadIdx.x;
    const float* ft = features + (size_t)bj * H_;
    float a0 = bf[f], a1 = 0.f;
#pragma unroll
    for (int h = 0; h < H_; h += 2) {
        a0 = fmaf(ft[h],     Wf[(h)     * F_ + f], a0);
        a1 = fmaf(ft[h + 1], Wf[(h + 1) * F_ + f], a1);
    }
    g_nf[(size_t)bj * F_ + f] = a0 + a1;
}

// ---------------- main fused kernel ----------------
struct __align__(16) SmemT {
    float b1[128];
    float b2[128];
    float jm[192];
    float agg[128];
    float o1[128];
    __align__(16) __half A [192 * PA];   // 27648 B  rbf fp16 (cols 50..63 zero)
    __align__(16) __half W1[64  * PB];   // 17408 B  [g][k] (rows 50..63 zero)
    __align__(16) __half W2[128 * PB];   // 34816 B  [k][f]
    __align__(16) __half Hs[192 * PB];   // 52224 B  softplus(rbf@W1+b1) fp16
};

__global__ __launch_bounds__(512, 1)
void main_kernel(const float* __restrict__ rbf,
                 const int*   __restrict__ mask,
                 const float* __restrict__ features,
                 const float* __restrict__ W1g, const float* __restrict__ b1g,
                 const float* __restrict__ W2g, const float* __restrict__ b2g,
                 const float* __restrict__ Wo1, const float* __restrict__ bo1,
                 const float* __restrict__ Wo2, const float* __restrict__ bo2,
                 float* __restrict__ out) {
    extern __shared__ char smem_raw[];
    SmemT& S = *reinterpret_cast<SmemT*>(smem_raw);
    const int tid = threadIdx.x;
    const int w   = tid >> 5;
    const int lid = tid & 31;
    const int bi  = blockIdx.x;
    const int b   = bi / N_;

    const int mw = w & 3;                 // M-warp index (4)
    const int nw = w >> 2;                // N-warp index (4)
    const int m_base = mw * 48;           // 3 m16 tiles per warp
    const int n_base = nw * 32;           // 4 n8 tiles per warp
    const int g_  = lid >> 2;             // row group 0..7
    const int tig = lid & 3;              // thread-in-group

    // ldmatrix lane geometry: row_off 0..15, col_off {0,8}
    const int sub = lid >> 3, r8 = lid & 7;
    const int row_off = r8 + (sub & 1) * 8;
    const int col_off = (sub >> 1) * 8;

    const uint32_t A_u  = smem_u32(S.A);
    const uint32_t W1_u = smem_u32(S.W1);
    const uint32_t W2_u = smem_u32(S.W2);
    const uint32_t Hs_u = smem_u32(S.Hs);

    // ---- phase 0a: zero padded regions + agg ----
    {
        float4 z = make_float4(0.f, 0.f, 0.f, 0.f);
        float4* a4 = reinterpret_cast<float4*>(S.A);
        for (int i = tid; i < (192 * PA) / 8; i += 512) a4[i] = z;
        float4* w14 = reinterpret_cast<float4*>(S.W1);
        for (int i = tid; i < (64 * PB) / 8; i += 512) w14[i] = z;
        if (tid < 128) S.agg[tid] = 0.f;
    }
    __syncthreads();

    // ---- phase 0b: stage fp16 operands + biases + mask ----
    {
        const float* rt = rbf + (size_t)bi * (N_ * G_);
        for (int idx = tid; idx < 192 * 25; idx += 512) {         // rbf: 25 float2/row
            int j = idx / 25, p = (idx - j * 25) * 2;
            float2 v = *reinterpret_cast<const float2*>(rt + j * G_ + p);
            *reinterpret_cast<__half2*>(&S.A[j * PA + p]) = __floats2half2_rn(v.x, v.y);
        }
        for (int idx = tid; idx < 50 * 64; idx += 512) {          // W1 [g][k]
            int gg = idx >> 6, p = (idx & 63) * 2;
            float2 v = *reinterpret_cast<const float2*>(W1g + gg * F_ + p);
            *reinterpret_cast<__half2*>(&S.W1[gg * PB + p]) = __floats2half2_rn(v.x, v.y);
        }
        for (int idx = tid; idx < 128 * 64; idx += 512) {         // W2 [k][f]
            int k = idx >> 6, p = (idx & 63) * 2;
            float2 v = *reinterpret_cast<const float2*>(W2g + k * F_ + p);
            *reinterpret_cast<__half2*>(&S.W2[k * PB + p]) = __floats2half2_rn(v.x, v.y);
        }
        if (tid < 128) { S.b1[tid] = b1g[tid]; S.b2[tid] = b2g[tid]; }
        if (tid < 192) S.jm[tid] = (float)mask[(size_t)bi * N_ + tid];
    }
    __syncthreads();

    // ---- GEMM1: D1 = rbf @ W1   (M=192,N=128,K=64) ----
    float c1[3][4][4];
#pragma unroll
    for (int mi = 0; mi < 3; mi++)
#pragma unroll
        for (int ni = 0; ni < 4; ni++)
#pragma unroll
            for (int q = 0; q < 4; q++) c1[mi][ni][q] = 0.f;

#pragma unroll
    for (int ks = 0; ks < 4; ks++) {
        uint32_t a[3][4];
#pragma unroll
        for (int mi = 0; mi < 3; mi++) {
            uint32_t addr = A_u + ((m_base + mi * 16 + row_off) * PA + ks * 16 + col_off) * 2;
            ldsm_x4(addr, a[mi][0], a[mi][1], a[mi][2], a[mi][3]);
        }
        uint32_t bb[2][4];
#pragma unroll
        for (int np = 0; np < 2; np++) {
            uint32_t addr = W1_u + ((ks * 16 + row_off) * PB + n_base + np * 16 + col_off) * 2;
            ldsm_x4_t(addr, bb[np][0], bb[np][1], bb[np][2], bb[np][3]);
        }
#pragma unroll
        for (int mi = 0; mi < 3; mi++)
#pragma unroll
            for (int ni = 0; ni < 4; ni++)
                mma16816(c1[mi][ni], a[mi][0], a[mi][1], a[mi][2], a[mi][3],
                         bb[ni >> 1][(ni & 1) * 2], bb[ni >> 1][(ni & 1) * 2 + 1]);
    }

    // ---- epilogue1: softplus(D1+b1) -> Hs fp16 ----
#pragma unroll
    for (int ni = 0; ni < 4; ni++) {
        const int k0 = n_base + ni * 8 + 2 * tig;
        const float bb0 = S.b1[k0], bb1 = S.b1[k0 + 1];
#pragma unroll
        for (int mi = 0; mi < 3; mi++) {
            const int j0 = m_base + mi * 16 + g_;
            float v0 = softplus_f(c1[mi][ni][0] + bb0);
            float v1 = softplus_f(c1[mi][ni][1] + bb1);
            float v2 = softplus_f(c1[mi][ni][2] + bb0);
            float v3 = softplus_f(c1[mi][ni][3] + bb1);
            *reinterpret_cast<__half2*>(&S.Hs[j0 * PB + k0])       = __floats2half2_rn(v0, v1);
            *reinterpret_cast<__half2*>(&S.Hs[(j0 + 8) * PB + k0]) = __floats2half2_rn(v2, v3);
        }
    }
    __syncthreads();

    // ---- GEMM2: D2 = Hs @ W2   (M=192,N=128,K=128) ----
    float c2[3][4][4];
#pragma unroll
    for (int mi = 0; mi < 3; mi++)
#pragma unroll
        for (int ni = 0; ni < 4; ni++)
#pragma unroll
            for (int q = 0; q < 4; q++) c2[mi][ni][q] = 0.f;

#pragma unroll
    for (int ks = 0; ks < 8; ks++) {
        uint32_t a[3][4];
#pragma unroll
        for (int mi = 0; mi < 3; mi++) {
            uint32_t addr = Hs_u + ((m_base + mi * 16 + row_off) * PB + ks * 16 + col_off) * 2;
            ldsm_x4(addr, a[mi][0], a[mi][1], a[mi][2], a[mi][3]);
        }
        uint32_t bb[2][4];
#pragma unroll
        for (int np = 0; np < 2; np++) {
            uint32_t addr = W2_u + ((ks * 16 + row_off) * PB + n_base + np * 16 + col_off) * 2;
            ldsm_x4_t(addr, bb[np][0], bb[np][1], bb[np][2], bb[np][3]);
        }
#pragma unroll
        for (int mi = 0; mi < 3; mi++)
#pragma unroll
            for (int ni = 0; ni < 4; ni++)
                mma16816(c2[mi][ni], a[mi][0], a[mi][1], a[mi][2], a[mi][3],
                         bb[ni >> 1][(ni & 1) * 2], bb[ni >> 1][(ni & 1) * 2 + 1]);
    }

    // ---- epilogue2: agg[f] += sum_j mask_j * nf[j,f] * (D2[j,f]+b2[f]) ----
    {
        float sumf[4][2];
#pragma unroll
        for (int ni = 0; ni < 4; ni++) { sumf[ni][0] = 0.f; sumf[ni][1] = 0.f; }

#pragma unroll
        for (int ni = 0; ni < 4; ni++) {
            const int f0 = n_base + ni * 8 + 2 * tig;
            const float bb0 = S.b2[f0], bb1 = S.b2[f0 + 1];
#pragma unroll
            for (int mi = 0; mi < 3; mi++) {
                const int j0 = m_base + mi * 16 + g_;
                const int j1 = j0 + 8;
                float2 nf0 = *reinterpret_cast<const float2*>(
                    g_nf + ((size_t)b * N_ + j0) * F_ + f0);
                float2 nf1 = *reinterpret_cast<const float2*>(
                    g_nf + ((size_t)b * N_ + j1) * F_ + f0);
                float w0 = S.jm[j0], w1 = S.jm[j1];
                sumf[ni][0] += w0 * nf0.x * (c2[mi][ni][0] + bb0)
                             + w1 * nf1.x * (c2[mi][ni][2] + bb0);
                sumf[ni][1] += w0 * nf0.y * (c2[mi][ni][1] + bb1)
                             + w1 * nf1.y * (c2[mi][ni][3] + bb1);
            }
        }
#pragma unroll
        for (int ni = 0; ni < 4; ni++)
#pragma unroll
            for (int q = 0; q < 2; q++) {
                float v = sumf[ni][q];
                v += __shfl_xor_sync(0xFFFFFFFFu, v, 4);
                v += __shfl_xor_sync(0xFFFFFFFFu, v, 8);
                v += __shfl_xor_sync(0xFFFFFFFFu, v, 16);
                if (lid < 4)
                    atomicAdd(&S.agg[n_base + ni * 8 + 2 * tig + q], v);
            }
    }
    __syncthreads();

    // ---- dense_out tail: out = features + softplus(agg@Wo1+bo1)@Wo2 + bo2 ----
    if (tid < 128) {
        const int h = tid;
        float a0 = bo1[h], a1 = 0.f;
#pragma unroll 8
        for (int f2 = 0; f2 < F_; f2 += 2) {
            a0 = fmaf(S.agg[f2],     Wo1[(f2)     * H_ + h], a0);
            a1 = fmaf(S.agg[f2 + 1], Wo1[(f2 + 1) * H_ + h], a1);
        }
        S.o1[h] = softplus_f(a0 + a1);
    }
    __syncthreads();
    if (tid < 128) {
        const int h = tid;
        float a0 = bo2[h] + features[(size_t)bi * H_ + h], a1 = 0.f;
#pragma unroll 8
        for (int hp = 0; hp < H_; hp += 2) {
            a0 = fmaf(S.o1[hp],     Wo2[(hp)     * H_ + h], a0);
            a1 = fmaf(S.o1[hp + 1], Wo2[(hp + 1) * H_ + h], a1);
        }
        out[(size_t)bi * H_ + h] = a0 + a1;
    }
}

// ---------------------------------------------------------------------------
extern "C" void kernel_launch(void* const* d_in, const int* in_sizes, int n_in,
                              void* d_out, int out_size) {
    const float* features = (const float*)d_in[0];
    const float* rbf      = (const float*)d_in[1];
    const int*   mask     = (const int*)  d_in[2];
    const float* W_rbf1   = (const float*)d_in[3];
    const float* b_rbf1   = (const float*)d_in[4];
    const float* W_rbf2   = (const float*)d_in[5];
    const float* b_rbf2   = (const float*)d_in[6];
    const float* W_f      = (const float*)d_in[7];
    const float* b_f      = (const float*)d_in[8];
    const float* W_o1     = (const float*)d_in[9];
    const float* b_o1     = (const float*)d_in[10];
    const float* W_o2     = (const float*)d_in[11];
    const float* b_o2     = (const float*)d_in[12];
    float* out = (float*)d_out;

    cudaFuncSetAttribute(main_kernel,
                         cudaFuncAttributeMaxDynamicSharedMemorySize,
                         (int)sizeof(SmemT));

    nf_kernel<<<BN_, 128>>>(features, W_f, b_f);
    main_kernel<<<BN_, 512, sizeof(SmemT)>>>(rbf, mask, features,
                                             W_rbf1, b_rbf1, W_rbf2, b_rbf2,
                                             W_o1, b_o1, W_o2, b_o2, out);
}

// round 5
// speedup vs baseline: 4.3760x; 1.2325x over previous
#include <cuda_runtime.h>
#include <cuda_fp16.h>
#include <cstdint>
#include <cstddef>

#define B_  16
#define N_  192
#define H_  128
#define F_  128
#define G_  50
#define BN_ (B_*N_)

#define PA  72    // A (rbf) pitch in halves
#define PB  136   // W1/W2/Hs pitch in halves

// ---------------- global scratch ----------------
__device__ float g_nf[BN_ * F_];          // nf = features@W_f + b_f
__device__ float g_aggp[2 * BN_ * F_];    // per-half-CTA partial aggregation

__device__ __forceinline__ float softplus_f(float x) {
    return fmaxf(x, 0.f) + __logf(1.f + __expf(-fabsf(x)));
}

__device__ __forceinline__ uint32_t smem_u32(const void* p) {
    uint32_t a;
    asm("{ .reg .u64 t; cvta.to.shared.u64 t, %1; cvt.u32.u64 %0, t; }" : "=r"(a) : "l"(p));
    return a;
}

__device__ __forceinline__ void ldsm_x4(uint32_t addr, uint32_t& r0, uint32_t& r1,
                                        uint32_t& r2, uint32_t& r3) {
    asm volatile("ldmatrix.sync.aligned.m8n8.x4.shared.b16 {%0,%1,%2,%3}, [%4];"
                 : "=r"(r0), "=r"(r1), "=r"(r2), "=r"(r3) : "r"(addr));
}
__device__ __forceinline__ void ldsm_x4_t(uint32_t addr, uint32_t& r0, uint32_t& r1,
                                          uint32_t& r2, uint32_t& r3) {
    asm volatile("ldmatrix.sync.aligned.m8n8.x4.trans.shared.b16 {%0,%1,%2,%3}, [%4];"
                 : "=r"(r0), "=r"(r1), "=r"(r2), "=r"(r3) : "r"(addr));
}
__device__ __forceinline__ void mma16816(float* c, uint32_t a0, uint32_t a1,
                                         uint32_t a2, uint32_t a3,
                                         uint32_t b0, uint32_t b1) {
    asm volatile(
        "mma.sync.aligned.m16n8k16.row.col.f32.f16.f16.f32 "
        "{%0,%1,%2,%3}, {%4,%5,%6,%7}, {%8,%9}, {%0,%1,%2,%3};"
        : "+f"(c[0]), "+f"(c[1]), "+f"(c[2]), "+f"(c[3])
        : "r"(a0), "r"(a1), "r"(a2), "r"(a3), "r"(b0), "r"(b1));
}

// ---------------- prep kernel: nf ----------------
__global__ void nf_kernel(const float* __restrict__ features,
                          const float* __restrict__ Wf,
                          const float* __restrict__ bf) {
    int bj = blockIdx.x;
    int f  = threadIdx.x;
    const float* ft = features + (size_t)bj * H_;
    float a0 = bf[f], a1 = 0.f;
#pragma unroll
    for (int h = 0; h < H_; h += 2) {
        a0 = fmaf(ft[h],     Wf[(h)     * F_ + f], a0);
        a1 = fmaf(ft[h + 1], Wf[(h + 1) * F_ + f], a1);
    }
    g_nf[(size_t)bj * F_ + f] = a0 + a1;
}

// ---------------- main fused kernel: one CTA per (b,i,half) ----------------
struct __align__(16) SmemT {
    float b1[128];
    float b2[128];
    float jm[96];
    float agg[128];
    __align__(16) __half A [96  * PA];   // 13824 B  rbf fp16 half-tile (cols 50..63 zero)
    __align__(16) __half W1[64  * PB];   // 17408 B  [g][k] (rows 50..63 zero)
    __align__(16) __half W2[128 * PB];   // 34816 B  [k][f]
    __align__(16) __half Hs[96  * PB];   // 26112 B  softplus(rbf@W1+b1) fp16
};

__global__ __launch_bounds__(256, 2)
void main_kernel(const float* __restrict__ rbf,
                 const int*   __restrict__ mask,
                 const float* __restrict__ W1g, const float* __restrict__ b1g,
                 const float* __restrict__ W2g, const float* __restrict__ b2g) {
    extern __shared__ char smem_raw[];
    SmemT& S = *reinterpret_cast<SmemT*>(smem_raw);
    const int tid  = threadIdx.x;
    const int w    = tid >> 5;
    const int lid  = tid & 31;
    const int bi   = blockIdx.x >> 1;
    const int half = blockIdx.x & 1;
    const int b    = bi / N_;
    const int jglo = half * 96;          // global j offset of this half-tile

    const int mw = w & 1;                // M-warp index (2)
    const int nw = w >> 1;               // N-warp index (4)
    const int m_base = mw * 48;          // 3 m16 tiles per warp (local rows)
    const int n_base = nw * 32;          // 4 n8 tiles per warp
    const int g_  = lid >> 2;            // row group 0..7
    const int tig = lid & 3;             // thread-in-group

    // ldmatrix lane geometry
    const int sub = lid >> 3, r8 = lid & 7;
    const int row_off = r8 + (sub & 1) * 8;
    const int col_off = (sub >> 1) * 8;

    const uint32_t A_u  = smem_u32(S.A);
    const uint32_t W1_u = smem_u32(S.W1);
    const uint32_t W2_u = smem_u32(S.W2);
    const uint32_t Hs_u = smem_u32(S.Hs);

    // ---- phase 0a: zero padded regions + agg ----
    {
        float4 z = make_float4(0.f, 0.f, 0.f, 0.f);
        float4* a4 = reinterpret_cast<float4*>(S.A);
        for (int i = tid; i < (96 * PA) / 8; i += 256) a4[i] = z;
        float4* w14 = reinterpret_cast<float4*>(S.W1);
        for (int i = tid; i < (64 * PB) / 8; i += 256) w14[i] = z;
        if (tid < 128) S.agg[tid] = 0.f;
    }
    __syncthreads();

    // ---- phase 0b: stage fp16 operands + biases + mask ----
    {
        const float* rt = rbf + ((size_t)bi * N_ + jglo) * G_;
        for (int idx = tid; idx < 96 * 25; idx += 256) {          // rbf: 25 float2/row
            int j = idx / 25, p = (idx - j * 25) * 2;
            float2 v = *reinterpret_cast<const float2*>(rt + j * G_ + p);
            *reinterpret_cast<__half2*>(&S.A[j * PA + p]) = __floats2half2_rn(v.x, v.y);
        }
        for (int idx = tid; idx < 50 * 64; idx += 256) {          // W1 [g][k]
            int gg = idx >> 6, p = (idx & 63) * 2;
            float2 v = *reinterpret_cast<const float2*>(W1g + gg * F_ + p);
            *reinterpret_cast<__half2*>(&S.W1[gg * PB + p]) = __floats2half2_rn(v.x, v.y);
        }
        for (int idx = tid; idx < 128 * 64; idx += 256) {         // W2 [k][f]
            int k = idx >> 6, p = (idx & 63) * 2;
            float2 v = *reinterpret_cast<const float2*>(W2g + k * F_ + p);
            *reinterpret_cast<__half2*>(&S.W2[k * PB + p]) = __floats2half2_rn(v.x, v.y);
        }
        if (tid < 128) { S.b1[tid] = b1g[tid]; S.b2[tid] = b2g[tid]; }
        if (tid < 96) S.jm[tid] = (float)mask[(size_t)bi * N_ + jglo + tid];
    }
    __syncthreads();

    // ---- GEMM1: D1 = rbf @ W1   (M=96,N=128,K=64) ----
    float c1[3][4][4];
#pragma unroll
    for (int mi = 0; mi < 3; mi++)
#pragma unroll
        for (int ni = 0; ni < 4; ni++)
#pragma unroll
            for (int q = 0; q < 4; q++) c1[mi][ni][q] = 0.f;

#pragma unroll
    for (int ks = 0; ks < 4; ks++) {
        uint32_t a[3][4];
#pragma unroll
        for (int mi = 0; mi < 3; mi++) {
            uint32_t addr = A_u + ((m_base + mi * 16 + row_off) * PA + ks * 16 + col_off) * 2;
            ldsm_x4(addr, a[mi][0], a[mi][1], a[mi][2], a[mi][3]);
        }
        uint32_t bb[2][4];
#pragma unroll
        for (int np = 0; np < 2; np++) {
            uint32_t addr = W1_u + ((ks * 16 + row_off) * PB + n_base + np * 16 + col_off) * 2;
            ldsm_x4_t(addr, bb[np][0], bb[np][1], bb[np][2], bb[np][3]);
        }
#pragma unroll
        for (int mi = 0; mi < 3; mi++)
#pragma unroll
            for (int ni = 0; ni < 4; ni++)
                mma16816(c1[mi][ni], a[mi][0], a[mi][1], a[mi][2], a[mi][3],
                         bb[ni >> 1][(ni & 1) * 2], bb[ni >> 1][(ni & 1) * 2 + 1]);
    }

    // ---- epilogue1: softplus(D1+b1) -> Hs fp16 ----
#pragma unroll
    for (int ni = 0; ni < 4; ni++) {
        const int k0 = n_base + ni * 8 + 2 * tig;
        const float bb0 = S.b1[k0], bb1 = S.b1[k0 + 1];
#pragma unroll
        for (int mi = 0; mi < 3; mi++) {
            const int j0 = m_base + mi * 16 + g_;
            float v0 = softplus_f(c1[mi][ni][0] + bb0);
            float v1 = softplus_f(c1[mi][ni][1] + bb1);
            float v2 = softplus_f(c1[mi][ni][2] + bb0);
            float v3 = softplus_f(c1[mi][ni][3] + bb1);
            *reinterpret_cast<__half2*>(&S.Hs[j0 * PB + k0])       = __floats2half2_rn(v0, v1);
            *reinterpret_cast<__half2*>(&S.Hs[(j0 + 8) * PB + k0]) = __floats2half2_rn(v2, v3);
        }
    }
    __syncthreads();

    // ---- GEMM2: D2 = Hs @ W2   (M=96,N=128,K=128) ----
    float c2[3][4][4];
#pragma unroll
    for (int mi = 0; mi < 3; mi++)
#pragma unroll
        for (int ni = 0; ni < 4; ni++)
#pragma unroll
            for (int q = 0; q < 4; q++) c2[mi][ni][q] = 0.f;

#pragma unroll
    for (int ks = 0; ks < 8; ks++) {
        uint32_t a[3][4];
#pragma unroll
        for (int mi = 0; mi < 3; mi++) {
            uint32_t addr = Hs_u + ((m_base + mi * 16 + row_off) * PB + ks * 16 + col_off) * 2;
            ldsm_x4(addr, a[mi][0], a[mi][1], a[mi][2], a[mi][3]);
        }
        uint32_t bb[2][4];
#pragma unroll
        for (int np = 0; np < 2; np++) {
            uint32_t addr = W2_u + ((ks * 16 + row_off) * PB + n_base + np * 16 + col_off) * 2;
            ldsm_x4_t(addr, bb[np][0], bb[np][1], bb[np][2], bb[np][3]);
        }
#pragma unroll
        for (int mi = 0; mi < 3; mi++)
#pragma unroll
            for (int ni = 0; ni < 4; ni++)
                mma16816(c2[mi][ni], a[mi][0], a[mi][1], a[mi][2], a[mi][3],
                         bb[ni >> 1][(ni & 1) * 2], bb[ni >> 1][(ni & 1) * 2 + 1]);
    }

    // ---- epilogue2: agg[f] += sum_j mask_j * nf[j,f] * (D2[j,f]+b2[f]) ----
    {
        float sumf[4][2];
#pragma unroll
        for (int ni = 0; ni < 4; ni++) { sumf[ni][0] = 0.f; sumf[ni][1] = 0.f; }

#pragma unroll
        for (int ni = 0; ni < 4; ni++) {
            const int f0 = n_base + ni * 8 + 2 * tig;
            const float bb0 = S.b2[f0], bb1 = S.b2[f0 + 1];
#pragma unroll
            for (int mi = 0; mi < 3; mi++) {
                const int j0 = m_base + mi * 16 + g_;   // local row
                const int j1 = j0 + 8;
                float2 nf0 = *reinterpret_cast<const float2*>(
                    g_nf + ((size_t)b * N_ + jglo + j0) * F_ + f0);
                float2 nf1 = *reinterpret_cast<const float2*>(
                    g_nf + ((size_t)b * N_ + jglo + j1) * F_ + f0);
                float w0 = S.jm[j0], w1 = S.jm[j1];
                sumf[ni][0] += w0 * nf0.x * (c2[mi][ni][0] + bb0)
                             + w1 * nf1.x * (c2[mi][ni][2] + bb0);
                sumf[ni][1] += w0 * nf0.y * (c2[mi][ni][1] + bb1)
                             + w1 * nf1.y * (c2[mi][ni][3] + bb1);
            }
        }
#pragma unroll
        for (int ni = 0; ni < 4; ni++)
#pragma unroll
            for (int q = 0; q < 2; q++) {
                float v = sumf[ni][q];
                v += __shfl_xor_sync(0xFFFFFFFFu, v, 4);
                v += __shfl_xor_sync(0xFFFFFFFFu, v, 8);
                v += __shfl_xor_sync(0xFFFFFFFFu, v, 16);
                if (lid < 4)
                    atomicAdd(&S.agg[n_base + ni * 8 + 2 * tig + q], v);
            }
    }
    __syncthreads();

    // ---- store partial agg (deterministic: per-half slot, no global atomics) ----
    if (tid < 128) g_aggp[(size_t)blockIdx.x * F_ + tid] = S.agg[tid];
}

// ---------------- dense_out kernel: out = features + MLP(agg) ----------------
__global__ void out_kernel(const float* __restrict__ features,
                           const float* __restrict__ Wo1, const float* __restrict__ bo1,
                           const float* __restrict__ Wo2, const float* __restrict__ bo2,
                           float* __restrict__ out) {
    __shared__ float agg[128];
    __shared__ float o1[128];
    const int bi = blockIdx.x;
    const int h  = threadIdx.x;

    agg[h] = g_aggp[(size_t)(2 * bi) * F_ + h] + g_aggp[(size_t)(2 * bi + 1) * F_ + h];
    __syncthreads();

    float a0 = bo1[h], a1 = 0.f;
#pragma unroll 8
    for (int f2 = 0; f2 < F_; f2 += 2) {
        a0 = fmaf(agg[f2],     Wo1[(f2)     * H_ + h], a0);
        a1 = fmaf(agg[f2 + 1], Wo1[(f2 + 1) * H_ + h], a1);
    }
    o1[h] = softplus_f(a0 + a1);
    __syncthreads();

    float c0 = bo2[h] + features[(size_t)bi * H_ + h], c1 = 0.f;
#pragma unroll 8
    for (int hp = 0; hp < H_; hp += 2) {
        c0 = fmaf(o1[hp],     Wo2[(hp)     * H_ + h], c0);
        c1 = fmaf(o1[hp + 1], Wo2[(hp + 1) * H_ + h], c1);
    }
    out[(size_t)bi * H_ + h] = c0 + c1;
}

// ---------------------------------------------------------------------------
extern "C" void kernel_launch(void* const* d_in, const int* in_sizes, int n_in,
                              void* d_out, int out_size) {
    const float* features = (const float*)d_in[0];
    const float* rbf      = (const float*)d_in[1];
    const int*   mask     = (const int*)  d_in[2];
    const float* W_rbf1   = (const float*)d_in[3];
    const float* b_rbf1   = (const float*)d_in[4];
    const float* W_rbf2   = (const float*)d_in[5];
    const float* b_rbf2   = (const float*)d_in[6];
    const float* W_f      = (const float*)d_in[7];
    const float* b_f      = (const float*)d_in[8];
    const float* W_o1     = (const float*)d_in[9];
    const float* b_o1     = (const float*)d_in[10];
    const float* W_o2     = (const float*)d_in[11];
    const float* b_o2     = (const float*)d_in[12];
    float* out = (float*)d_out;

    cudaFuncSetAttribute(main_kernel,
                         cudaFuncAttributeMaxDynamicSharedMemorySize,
                         (int)sizeof(SmemT));

    nf_kernel<<<BN_, 128>>>(features, W_f, b_f);
    main_kernel<<<2 * BN_, 256, sizeof(SmemT)>>>(rbf, mask,
                                                 W_rbf1, b_rbf1, W_rbf2, b_rbf2);
    out_kernel<<<BN_, 128>>>(features, W_o1, b_o1, W_o2, b_o2, out);
}

// round 16
// speedup vs baseline: 6.5973x; 1.5076x over previous
#include <cuda_runtime.h>
#include <cuda_fp16.h>
#include <cstdint>
#include <cstddef>

#define B_  16
#define N_  192
#define H_  128
#define F_  128
#define G_  50
#define BN_ (B_*N_)
#define TILES_ (2*BN_)
#define GRID_MAIN 296

#define PA  72    // A (rbf) pitch in halves
#define PB  136   // W1/W2/Hs pitch in halves

// ---------------- global scratch ----------------
__device__ float g_nf[BN_ * F_];                 // nf = features@W_f + b_f
__device__ float g_aggp[TILES_ * F_];            // per-half-tile partial aggregation
__device__ __align__(16) __half g_W1h[64  * PB]; // W1 fp16 [g][k], padded
__device__ __align__(16) __half g_W2h[128 * PB]; // W2 fp16 [k][f], padded

__device__ __forceinline__ float softplus_f(float x) {
    return fmaxf(x, 0.f) + __logf(1.f + __expf(-fabsf(x)));
}

__device__ __forceinline__ uint32_t smem_u32(const void* p) {
    uint32_t a;
    asm("{ .reg .u64 t; cvta.to.shared.u64 t, %1; cvt.u32.u64 %0, t; }" : "=r"(a) : "l"(p));
    return a;
}

__device__ __forceinline__ void ldsm_x4(uint32_t addr, uint32_t& r0, uint32_t& r1,
                                        uint32_t& r2, uint32_t& r3) {
    asm volatile("ldmatrix.sync.aligned.m8n8.x4.shared.b16 {%0,%1,%2,%3}, [%4];"
                 : "=r"(r0), "=r"(r1), "=r"(r2), "=r"(r3) : "r"(addr));
}
__device__ __forceinline__ void ldsm_x4_t(uint32_t addr, uint32_t& r0, uint32_t& r1,
                                          uint32_t& r2, uint32_t& r3) {
    asm volatile("ldmatrix.sync.aligned.m8n8.x4.trans.shared.b16 {%0,%1,%2,%3}, [%4];"
                 : "=r"(r0), "=r"(r1), "=r"(r2), "=r"(r3) : "r"(addr));
}
__device__ __forceinline__ void mma16816(float* c, uint32_t a0, uint32_t a1,
                                         uint32_t a2, uint32_t a3,
                                         uint32_t b0, uint32_t b1) {
    asm volatile(
        "mma.sync.aligned.m16n8k16.row.col.f32.f16.f16.f32 "
        "{%0,%1,%2,%3}, {%4,%5,%6,%7}, {%8,%9}, {%0,%1,%2,%3};"
        : "+f"(c[0]), "+f"(c[1]), "+f"(c[2]), "+f"(c[3])
        : "r"(a0), "r"(a1), "r"(a2), "r"(a3), "r"(b0), "r"(b1));
}

// ---------------- prep: fp16 weight conversion ----------------
__global__ void prep_weights(const float* __restrict__ W1g,
                             const float* __restrict__ W2g) {
    int stride = gridDim.x * blockDim.x;
    int t0 = blockIdx.x * blockDim.x + threadIdx.x;
    for (int idx = t0; idx < 64 * PB; idx += stride) {
        int row = idx / PB, col = idx - row * PB;
        g_W1h[idx] = (row < G_ && col < 128) ? __float2half(W1g[row * F_ + col]) : __half(0);
    }
    for (int idx = t0; idx < 128 * PB; idx += stride) {
        int row = idx / PB, col = idx - row * PB;
        g_W2h[idx] = (col < 128) ? __float2half(W2g[row * F_ + col]) : __half(0);
    }
}

// ---------------- nf kernel: 8 rows per block ----------------
__global__ void nf_kernel(const float* __restrict__ features,
                          const float* __restrict__ Wf,
                          const float* __restrict__ bf) {
    __shared__ float sf[8][128];
    const int f   = threadIdx.x;
    const int bj0 = blockIdx.x * 8;
    for (int idx = f; idx < 8 * 128; idx += 128) {
        int r = idx >> 7, c = idx & 127;
        sf[r][c] = features[(size_t)(bj0 + r) * H_ + c];
    }
    __syncthreads();
    float acc[8];
    const float bv = bf[f];
#pragma unroll
    for (int r = 0; r < 8; r++) acc[r] = bv;
#pragma unroll 4
    for (int h = 0; h < H_; h++) {
        float wv = Wf[h * F_ + f];
#pragma unroll
        for (int r = 0; r < 8; r++) acc[r] = fmaf(sf[r][h], wv, acc[r]);
    }
#pragma unroll
    for (int r = 0; r < 8; r++) g_nf[(size_t)(bj0 + r) * F_ + f] = acc[r];
}

// ---------------- main persistent kernel ----------------
struct __align__(16) SmemT {
    float b1[128];
    float b2[128];
    float jm[96];
    float agg[128];
    __align__(16) __half A [96  * PA];   // 13824 B  rbf fp16 (cols 50..63 zero)
    __align__(16) __half W1[64  * PB];   // 17408 B
    __align__(16) __half W2[128 * PB];   // 34816 B
    __align__(16) __half Hs[96  * PB];   // 26112 B
};

__global__ __launch_bounds__(256, 2)
void main_kernel(const float* __restrict__ rbf,
                 const int*   __restrict__ mask,
                 const float* __restrict__ b1g, const float* __restrict__ b2g) {
    extern __shared__ char smem_raw[];
    SmemT& S = *reinterpret_cast<SmemT*>(smem_raw);
    const int tid = threadIdx.x;
    const int w   = tid >> 5;
    const int lid = tid & 31;

    const int mw = w & 1;
    const int nw = w >> 1;
    const int m_base = mw * 48;
    const int n_base = nw * 32;
    const int g_  = lid >> 2;
    const int tig = lid & 3;

    const int sub = lid >> 3, r8 = lid & 7;
    const int row_off = r8 + (sub & 1) * 8;
    const int col_off = (sub >> 1) * 8;

    const uint32_t A_u  = smem_u32(S.A);
    const uint32_t W1_u = smem_u32(S.W1);
    const uint32_t W2_u = smem_u32(S.W2);
    const uint32_t Hs_u = smem_u32(S.Hs);

    // ---- one-time staging: weights (pre-converted fp16), biases, A pad, agg ----
    {
        float4 z = make_float4(0.f, 0.f, 0.f, 0.f);
        float4* a4 = reinterpret_cast<float4*>(S.A);
        for (int i = tid; i < (96 * PA) / 8; i += 256) a4[i] = z;
        const float4* s1 = reinterpret_cast<const float4*>(g_W1h);
        float4* d1 = reinterpret_cast<float4*>(S.W1);
        for (int i = tid; i < (64 * PB) / 8; i += 256) d1[i] = s1[i];
        const float4* s2 = reinterpret_cast<const float4*>(g_W2h);
        float4* d2 = reinterpret_cast<float4*>(S.W2);
        for (int i = tid; i < (128 * PB) / 8; i += 256) d2[i] = s2[i];
        if (tid < 128) { S.b1[tid] = b1g[tid]; S.b2[tid] = b2g[tid]; S.agg[tid] = 0.f; }
    }

    // ---- persistent tile loop ----
    for (int t = blockIdx.x; t < TILES_; t += GRID_MAIN) {
        const int bi   = t >> 1;
        const int half = t & 1;
        const int b    = bi / N_;
        const int jglo = half * 96;

        // stage rbf tile + mask (A pad cols stay zero across tiles)
        {
            const float* rt = rbf + ((size_t)bi * N_ + jglo) * G_;
            for (int idx = tid; idx < 96 * 25; idx += 256) {
                int j = idx / 25, p = (idx - j * 25) * 2;
                float2 v = *reinterpret_cast<const float2*>(rt + j * G_ + p);
                *reinterpret_cast<__half2*>(&S.A[j * PA + p]) = __floats2half2_rn(v.x, v.y);
            }
            if (tid < 96) S.jm[tid] = (float)mask[(size_t)bi * N_ + jglo + tid];
        }
        __syncthreads();

        // ---- GEMM1: D1 = rbf @ W1   (M=96,N=128,K=64) ----
        float c1[3][4][4];
#pragma unroll
        for (int mi = 0; mi < 3; mi++)
#pragma unroll
            for (int ni = 0; ni < 4; ni++)
#pragma unroll
                for (int q = 0; q < 4; q++) c1[mi][ni][q] = 0.f;

#pragma unroll
        for (int ks = 0; ks < 4; ks++) {
            uint32_t a[3][4];
#pragma unroll
            for (int mi = 0; mi < 3; mi++) {
                uint32_t addr = A_u + ((m_base + mi * 16 + row_off) * PA + ks * 16 + col_off) * 2;
                ldsm_x4(addr, a[mi][0], a[mi][1], a[mi][2], a[mi][3]);
            }
            uint32_t bb[2][4];
#pragma unroll
            for (int np = 0; np < 2; np++) {
                uint32_t addr = W1_u + ((ks * 16 + row_off) * PB + n_base + np * 16 + col_off) * 2;
                ldsm_x4_t(addr, bb[np][0], bb[np][1], bb[np][2], bb[np][3]);
            }
#pragma unroll
            for (int mi = 0; mi < 3; mi++)
#pragma unroll
                for (int ni = 0; ni < 4; ni++)
                    mma16816(c1[mi][ni], a[mi][0], a[mi][1], a[mi][2], a[mi][3],
                             bb[ni >> 1][(ni & 1) * 2], bb[ni >> 1][(ni & 1) * 2 + 1]);
        }

        // ---- epilogue1: softplus(D1+b1) -> Hs fp16 ----
#pragma unroll
        for (int ni = 0; ni < 4; ni++) {
            const int k0 = n_base + ni * 8 + 2 * tig;
            const float bb0 = S.b1[k0], bb1 = S.b1[k0 + 1];
#pragma unroll
            for (int mi = 0; mi < 3; mi++) {
                const int j0 = m_base + mi * 16 + g_;
                float v0 = softplus_f(c1[mi][ni][0] + bb0);
                float v1 = softplus_f(c1[mi][ni][1] + bb1);
                float v2 = softplus_f(c1[mi][ni][2] + bb0);
                float v3 = softplus_f(c1[mi][ni][3] + bb1);
                *reinterpret_cast<__half2*>(&S.Hs[j0 * PB + k0])       = __floats2half2_rn(v0, v1);
                *reinterpret_cast<__half2*>(&S.Hs[(j0 + 8) * PB + k0]) = __floats2half2_rn(v2, v3);
            }
        }
        __syncthreads();

        // ---- GEMM2: D2 = Hs @ W2   (M=96,N=128,K=128) ----
        float c2[3][4][4];
#pragma unroll
        for (int mi = 0; mi < 3; mi++)
#pragma unroll
            for (int ni = 0; ni < 4; ni++)
#pragma unroll
                for (int q = 0; q < 4; q++) c2[mi][ni][q] = 0.f;

#pragma unroll
        for (int ks = 0; ks < 8; ks++) {
            uint32_t a[3][4];
#pragma unroll
            for (int mi = 0; mi < 3; mi++) {
                uint32_t addr = Hs_u + ((m_base + mi * 16 + row_off) * PB + ks * 16 + col_off) * 2;
                ldsm_x4(addr, a[mi][0], a[mi][1], a[mi][2], a[mi][3]);
            }
            uint32_t bb[2][4];
#pragma unroll
            for (int np = 0; np < 2; np++) {
                uint32_t addr = W2_u + ((ks * 16 + row_off) * PB + n_base + np * 16 + col_off) * 2;
                ldsm_x4_t(addr, bb[np][0], bb[np][1], bb[np][2], bb[np][3]);
            }
#pragma unroll
            for (int mi = 0; mi < 3; mi++)
#pragma unroll
                for (int ni = 0; ni < 4; ni++)
                    mma16816(c2[mi][ni], a[mi][0], a[mi][1], a[mi][2], a[mi][3],
                             bb[ni >> 1][(ni & 1) * 2], bb[ni >> 1][(ni & 1) * 2 + 1]);
        }

        // ---- epilogue2: agg[f] += sum_j mask_j * nf[j,f] * (D2[j,f]+b2[f]) ----
        {
            float sumf[4][2];
#pragma unroll
            for (int ni = 0; ni < 4; ni++) { sumf[ni][0] = 0.f; sumf[ni][1] = 0.f; }

#pragma unroll
            for (int ni = 0; ni < 4; ni++) {
                const int f0 = n_base + ni * 8 + 2 * tig;
                const float bb0 = S.b2[f0], bb1 = S.b2[f0 + 1];
#pragma unroll
                for (int mi = 0; mi < 3; mi++) {
                    const int j0 = m_base + mi * 16 + g_;
                    const int j1 = j0 + 8;
                    float2 nf0 = *reinterpret_cast<const float2*>(
                        g_nf + ((size_t)b * N_ + jglo + j0) * F_ + f0);
                    float2 nf1 = *reinterpret_cast<const float2*>(
                        g_nf + ((size_t)b * N_ + jglo + j1) * F_ + f0);
                    float w0 = S.jm[j0], w1 = S.jm[j1];
                    sumf[ni][0] += w0 * nf0.x * (c2[mi][ni][0] + bb0)
                                 + w1 * nf1.x * (c2[mi][ni][2] + bb0);
                    sumf[ni][1] += w0 * nf0.y * (c2[mi][ni][1] + bb1)
                                 + w1 * nf1.y * (c2[mi][ni][3] + bb1);
                }
            }
#pragma unroll
            for (int ni = 0; ni < 4; ni++)
#pragma unroll
                for (int q = 0; q < 2; q++) {
                    float v = sumf[ni][q];
                    v += __shfl_xor_sync(0xFFFFFFFFu, v, 4);
                    v += __shfl_xor_sync(0xFFFFFFFFu, v, 8);
                    v += __shfl_xor_sync(0xFFFFFFFFu, v, 16);
                    if (lid < 4)
                        atomicAdd(&S.agg[n_base + ni * 8 + 2 * tig + q], v);
                }
        }
        __syncthreads();

        // store partial agg (deterministic), re-zero for next tile (same threads)
        if (tid < 128) {
            g_aggp[(size_t)t * F_ + tid] = S.agg[tid];
            S.agg[tid] = 0.f;
        }
    }
}

// ---------------- dense_out kernel: 8 (b,i) per block ----------------
__global__ void out_kernel(const float* __restrict__ features,
                           const float* __restrict__ Wo1, const float* __restrict__ bo1,
                           const float* __restrict__ Wo2, const float* __restrict__ bo2,
                           float* __restrict__ out) {
    __shared__ float agg[8][128];
    __shared__ float o1[8][128];
    const int h   = threadIdx.x;
    const int bi0 = blockIdx.x * 8;

    for (int idx = h; idx < 8 * 128; idx += 128) {
        int r = idx >> 7, c = idx & 127;
        agg[r][c] = g_aggp[(size_t)(2 * (bi0 + r))     * F_ + c]
                  + g_aggp[(size_t)(2 * (bi0 + r) + 1) * F_ + c];
    }
    __syncthreads();

    float acc[8];
    const float b1v = bo1[h];
#pragma unroll
    for (int r = 0; r < 8; r++) acc[r] = b1v;
#pragma unroll 4
    for (int f = 0; f < F_; f++) {
        float wv = Wo1[f * H_ + h];
#pragma unroll
        for (int r = 0; r < 8; r++) acc[r] = fmaf(agg[r][f], wv, acc[r]);
    }
#pragma unroll
    for (int r = 0; r < 8; r++) o1[r][h] = softplus_f(acc[r]);
    __syncthreads();

    float acc2[8];
    const float b2v = bo2[h];
#pragma unroll
    for (int r = 0; r < 8; r++)
        acc2[r] = b2v + features[(size_t)(bi0 + r) * H_ + h];
#pragma unroll 4
    for (int hp = 0; hp < H_; hp++) {
        float wv = Wo2[hp * H_ + h];
#pragma unroll
        for (int r = 0; r < 8; r++) acc2[r] = fmaf(o1[r][hp], wv, acc2[r]);
    }
#pragma unroll
    for (int r = 0; r < 8; r++) out[(size_t)(bi0 + r) * H_ + h] = acc2[r];
}

// ---------------------------------------------------------------------------
extern "C" void kernel_launch(void* const* d_in, const int* in_sizes, int n_in,
                              void* d_out, int out_size) {
    const float* features = (const float*)d_in[0];
    const float* rbf      = (const float*)d_in[1];
    const int*   mask     = (const int*)  d_in[2];
    const float* W_rbf1   = (const float*)d_in[3];
    const float* b_rbf1   = (const float*)d_in[4];
    const float* W_rbf2   = (const float*)d_in[5];
    const float* b_rbf2   = (const float*)d_in[6];
    const float* W_f      = (const float*)d_in[7];
    const float* b_f      = (const float*)d_in[8];
    const float* W_o1     = (const float*)d_in[9];
    const float* b_o1     = (const float*)d_in[10];
    const float* W_o2     = (const float*)d_in[11];
    const float* b_o2     = (const float*)d_in[12];
    float* out = (float*)d_out;

    cudaFuncSetAttribute(main_kernel,
                         cudaFuncAttributeMaxDynamicSharedMemorySize,
                         (int)sizeof(SmemT));

    prep_weights<<<32, 256>>>(W_rbf1, W_rbf2);
    nf_kernel<<<BN_ / 8, 128>>>(features, W_f, b_f);
    main_kernel<<<GRID_MAIN, 256, sizeof(SmemT)>>>(rbf, mask, b_rbf1, b_rbf2);
    out_kernel<<<BN_ / 8, 128>>>(features, W_o1, b_o1, W_o2, b_o2, out);
}

// round 17
// speedup vs baseline: 7.2739x; 1.1026x over previous
#include <cuda_runtime.h>
#include <cuda_fp16.h>
#include <cstdint>
#include <cstddef>

#define B_  16
#define N_  192
#define H_  128
#define F_  128
#define G_  50
#define BN_ (B_*N_)
#define TILES_ (2*BN_)
#define GRID_MAIN 296

#define PA  72    // A (rbf) pitch in halves
#define PB  136   // W1/W2/Hs pitch in halves

// ---------------- global scratch ----------------
__device__ float g_nf[BN_ * F_];                 // nf = features@W_f + b_f
__device__ float g_aggp[TILES_ * F_];            // per-half-tile partial aggregation
__device__ __align__(16) __half g_W1h[64  * PB]; // W1 fp16 [g][k], padded
__device__ __align__(16) __half g_W2h[128 * PB]; // W2 fp16 [k][f], padded

__device__ __forceinline__ float softplus_f(float x) {
    return fmaxf(x, 0.f) + __logf(1.f + __expf(-fabsf(x)));
}

__device__ __forceinline__ uint32_t smem_u32(const void* p) {
    uint32_t a;
    asm("{ .reg .u64 t; cvta.to.shared.u64 t, %1; cvt.u32.u64 %0, t; }" : "=r"(a) : "l"(p));
    return a;
}

__device__ __forceinline__ void ldsm_x4(uint32_t addr, uint32_t& r0, uint32_t& r1,
                                        uint32_t& r2, uint32_t& r3) {
    asm volatile("ldmatrix.sync.aligned.m8n8.x4.shared.b16 {%0,%1,%2,%3}, [%4];"
                 : "=r"(r0), "=r"(r1), "=r"(r2), "=r"(r3) : "r"(addr));
}
__device__ __forceinline__ void ldsm_x4_t(uint32_t addr, uint32_t& r0, uint32_t& r1,
                                          uint32_t& r2, uint32_t& r3) {
    asm volatile("ldmatrix.sync.aligned.m8n8.x4.trans.shared.b16 {%0,%1,%2,%3}, [%4];"
                 : "=r"(r0), "=r"(r1), "=r"(r2), "=r"(r3) : "r"(addr));
}
__device__ __forceinline__ void mma16816(float* c, uint32_t a0, uint32_t a1,
                                         uint32_t a2, uint32_t a3,
                                         uint32_t b0, uint32_t b1) {
    asm volatile(
        "mma.sync.aligned.m16n8k16.row.col.f32.f16.f16.f32 "
        "{%0,%1,%2,%3}, {%4,%5,%6,%7}, {%8,%9}, {%0,%1,%2,%3};"
        : "+f"(c[0]), "+f"(c[1]), "+f"(c[2]), "+f"(c[3])
        : "r"(a0), "r"(a1), "r"(a2), "r"(a3), "r"(b0), "r"(b1));
}

// ---------------- prep: fp16 weight conversion ----------------
__global__ void prep_weights(const float* __restrict__ W1g,
                             const float* __restrict__ W2g) {
    int stride = gridDim.x * blockDim.x;
    int t0 = blockIdx.x * blockDim.x + threadIdx.x;
    for (int idx = t0; idx < 64 * PB; idx += stride) {
        int row = idx / PB, col = idx - row * PB;
        g_W1h[idx] = (row < G_ && col < 128) ? __float2half(W1g[row * F_ + col]) : __half(0);
    }
    for (int idx = t0; idx < 128 * PB; idx += stride) {
        int row = idx / PB, col = idx - row * PB;
        g_W2h[idx] = (col < 128) ? __float2half(W2g[row * F_ + col]) : __half(0);
    }
}

// ---------------- nf kernel: 8 rows/block, 4-way k-split, 512 thr ----------------
__global__ __launch_bounds__(512)
void nf_kernel(const float* __restrict__ features,
               const float* __restrict__ Wf,
               const float* __restrict__ bf) {
    __shared__ float sf[8][128];
    __shared__ float part[4][8][128];
    const int tid = threadIdx.x;
    const int f   = tid & 127;
    const int q   = tid >> 7;          // 0..3
    const int bj0 = blockIdx.x * 8;

    for (int idx = tid; idx < 8 * 128; idx += 512) {
        int r = idx >> 7, c = idx & 127;
        sf[r][c] = features[(size_t)(bj0 + r) * H_ + c];
    }
    __syncthreads();

    float acc[8];
#pragma unroll
    for (int r = 0; r < 8; r++) acc[r] = 0.f;
    const int h0 = 32 * q;
#pragma unroll 8
    for (int h = h0; h < h0 + 32; h++) {
        float wv = Wf[h * F_ + f];
#pragma unroll
        for (int r = 0; r < 8; r++) acc[r] = fmaf(sf[r][h], wv, acc[r]);
    }
#pragma unroll
    for (int r = 0; r < 8; r++) part[q][r][f] = acc[r];
    __syncthreads();

    const float bv = bf[f];
#pragma unroll
    for (int rr = 0; rr < 2; rr++) {
        int r = 2 * q + rr;
        float s = bv + part[0][r][f] + part[1][r][f] + part[2][r][f] + part[3][r][f];
        g_nf[(size_t)(bj0 + r) * F_ + f] = s;
    }
}

// ---------------- main persistent kernel (unchanged) ----------------
struct __align__(16) SmemT {
    float b1[128];
    float b2[128];
    float jm[96];
    float agg[128];
    __align__(16) __half A [96  * PA];   // 13824 B  rbf fp16 (cols 50..63 zero)
    __align__(16) __half W1[64  * PB];   // 17408 B
    __align__(16) __half W2[128 * PB];   // 34816 B
    __align__(16) __half Hs[96  * PB];   // 26112 B
};

__global__ __launch_bounds__(256, 2)
void main_kernel(const float* __restrict__ rbf,
                 const int*   __restrict__ mask,
                 const float* __restrict__ b1g, const float* __restrict__ b2g) {
    extern __shared__ char smem_raw[];
    SmemT& S = *reinterpret_cast<SmemT*>(smem_raw);
    const int tid = threadIdx.x;
    const int w   = tid >> 5;
    const int lid = tid & 31;

    const int mw = w & 1;
    const int nw = w >> 1;
    const int m_base = mw * 48;
    const int n_base = nw * 32;
    const int g_  = lid >> 2;
    const int tig = lid & 3;

    const int sub = lid >> 3, r8 = lid & 7;
    const int row_off = r8 + (sub & 1) * 8;
    const int col_off = (sub >> 1) * 8;

    const uint32_t A_u  = smem_u32(S.A);
    const uint32_t W1_u = smem_u32(S.W1);
    const uint32_t W2_u = smem_u32(S.W2);
    const uint32_t Hs_u = smem_u32(S.Hs);

    // ---- one-time staging: weights (pre-converted fp16), biases, A pad, agg ----
    {
        float4 z = make_float4(0.f, 0.f, 0.f, 0.f);
        float4* a4 = reinterpret_cast<float4*>(S.A);
        for (int i = tid; i < (96 * PA) / 8; i += 256) a4[i] = z;
        const float4* s1 = reinterpret_cast<const float4*>(g_W1h);
        float4* d1 = reinterpret_cast<float4*>(S.W1);
        for (int i = tid; i < (64 * PB) / 8; i += 256) d1[i] = s1[i];
        const float4* s2 = reinterpret_cast<const float4*>(g_W2h);
        float4* d2 = reinterpret_cast<float4*>(S.W2);
        for (int i = tid; i < (128 * PB) / 8; i += 256) d2[i] = s2[i];
        if (tid < 128) { S.b1[tid] = b1g[tid]; S.b2[tid] = b2g[tid]; S.agg[tid] = 0.f; }
    }

    // ---- persistent tile loop ----
    for (int t = blockIdx.x; t < TILES_; t += GRID_MAIN) {
        const int bi   = t >> 1;
        const int half = t & 1;
        const int b    = bi / N_;
        const int jglo = half * 96;

        // stage rbf tile + mask (A pad cols stay zero across tiles)
        {
            const float* rt = rbf + ((size_t)bi * N_ + jglo) * G_;
            for (int idx = tid; idx < 96 * 25; idx += 256) {
                int j = idx / 25, p = (idx - j * 25) * 2;
                float2 v = *reinterpret_cast<const float2*>(rt + j * G_ + p);
                *reinterpret_cast<__half2*>(&S.A[j * PA + p]) = __floats2half2_rn(v.x, v.y);
            }
            if (tid < 96) S.jm[tid] = (float)mask[(size_t)bi * N_ + jglo + tid];
        }
        __syncthreads();

        // ---- GEMM1: D1 = rbf @ W1   (M=96,N=128,K=64) ----
        float c1[3][4][4];
#pragma unroll
        for (int mi = 0; mi < 3; mi++)
#pragma unroll
            for (int ni = 0; ni < 4; ni++)
#pragma unroll
                for (int q = 0; q < 4; q++) c1[mi][ni][q] = 0.f;

#pragma unroll
        for (int ks = 0; ks < 4; ks++) {
            uint32_t a[3][4];
#pragma unroll
            for (int mi = 0; mi < 3; mi++) {
                uint32_t addr = A_u + ((m_base + mi * 16 + row_off) * PA + ks * 16 + col_off) * 2;
                ldsm_x4(addr, a[mi][0], a[mi][1], a[mi][2], a[mi][3]);
            }
            uint32_t bb[2][4];
#pragma unroll
            for (int np = 0; np < 2; np++) {
                uint32_t addr = W1_u + ((ks * 16 + row_off) * PB + n_base + np * 16 + col_off) * 2;
                ldsm_x4_t(addr, bb[np][0], bb[np][1], bb[np][2], bb[np][3]);
            }
#pragma unroll
            for (int mi = 0; mi < 3; mi++)
#pragma unroll
                for (int ni = 0; ni < 4; ni++)
                    mma16816(c1[mi][ni], a[mi][0], a[mi][1], a[mi][2], a[mi][3],
                             bb[ni >> 1][(ni & 1) * 2], bb[ni >> 1][(ni & 1) * 2 + 1]);
        }

        // ---- epilogue1: softplus(D1+b1) -> Hs fp16 ----
#pragma unroll
        for (int ni = 0; ni < 4; ni++) {
            const int k0 = n_base + ni * 8 + 2 * tig;
            const float bb0 = S.b1[k0], bb1 = S.b1[k0 + 1];
#pragma unroll
            for (int mi = 0; mi < 3; mi++) {
                const int j0 = m_base + mi * 16 + g_;
                float v0 = softplus_f(c1[mi][ni][0] + bb0);
                float v1 = softplus_f(c1[mi][ni][1] + bb1);
                float v2 = softplus_f(c1[mi][ni][2] + bb0);
                float v3 = softplus_f(c1[mi][ni][3] + bb1);
                *reinterpret_cast<__half2*>(&S.Hs[j0 * PB + k0])       = __floats2half2_rn(v0, v1);
                *reinterpret_cast<__half2*>(&S.Hs[(j0 + 8) * PB + k0]) = __floats2half2_rn(v2, v3);
            }
        }
        __syncthreads();

        // ---- GEMM2: D2 = Hs @ W2   (M=96,N=128,K=128) ----
        float c2[3][4][4];
#pragma unroll
        for (int mi = 0; mi < 3; mi++)
#pragma unroll
            for (int ni = 0; ni < 4; ni++)
#pragma unroll
                for (int q = 0; q < 4; q++) c2[mi][ni][q] = 0.f;

#pragma unroll
        for (int ks = 0; ks < 8; ks++) {
            uint32_t a[3][4];
#pragma unroll
            for (int mi = 0; mi < 3; mi++) {
                uint32_t addr = Hs_u + ((m_base + mi * 16 + row_off) * PB + ks * 16 + col_off) * 2;
                ldsm_x4(addr, a[mi][0], a[mi][1], a[mi][2], a[mi][3]);
            }
            uint32_t bb[2][4];
#pragma unroll
            for (int np = 0; np < 2; np++) {
                uint32_t addr = W2_u + ((ks * 16 + row_off) * PB + n_base + np * 16 + col_off) * 2;
                ldsm_x4_t(addr, bb[np][0], bb[np][1], bb[np][2], bb[np][3]);
            }
#pragma unroll
            for (int mi = 0; mi < 3; mi++)
#pragma unroll
                for (int ni = 0; ni < 4; ni++)
                    mma16816(c2[mi][ni], a[mi][0], a[mi][1], a[mi][2], a[mi][3],
                             bb[ni >> 1][(ni & 1) * 2], bb[ni >> 1][(ni & 1) * 2 + 1]);
        }

        // ---- epilogue2: agg[f] += sum_j mask_j * nf[j,f] * (D2[j,f]+b2[f]) ----
        {
            float sumf[4][2];
#pragma unroll
            for (int ni = 0; ni < 4; ni++) { sumf[ni][0] = 0.f; sumf[ni][1] = 0.f; }

#pragma unroll
            for (int ni = 0; ni < 4; ni++) {
                const int f0 = n_base + ni * 8 + 2 * tig;
                const float bb0 = S.b2[f0], bb1 = S.b2[f0 + 1];
#pragma unroll
                for (int mi = 0; mi < 3; mi++) {
                    const int j0 = m_base + mi * 16 + g_;
                    const int j1 = j0 + 8;
                    float2 nf0 = *reinterpret_cast<const float2*>(
                        g_nf + ((size_t)b * N_ + jglo + j0) * F_ + f0);
                    float2 nf1 = *reinterpret_cast<const float2*>(
                        g_nf + ((size_t)b * N_ + jglo + j1) * F_ + f0);
                    float w0 = S.jm[j0], w1 = S.jm[j1];
                    sumf[ni][0] += w0 * nf0.x * (c2[mi][ni][0] + bb0)
                                 + w1 * nf1.x * (c2[mi][ni][2] + bb0);
                    sumf[ni][1] += w0 * nf0.y * (c2[mi][ni][1] + bb1)
                                 + w1 * nf1.y * (c2[mi][ni][3] + bb1);
                }
            }
#pragma unroll
            for (int ni = 0; ni < 4; ni++)
#pragma unroll
                for (int q = 0; q < 2; q++) {
                    float v = sumf[ni][q];
                    v += __shfl_xor_sync(0xFFFFFFFFu, v, 4);
                    v += __shfl_xor_sync(0xFFFFFFFFu, v, 8);
                    v += __shfl_xor_sync(0xFFFFFFFFu, v, 16);
                    if (lid < 4)
                        atomicAdd(&S.agg[n_base + ni * 8 + 2 * tig + q], v);
                }
        }
        __syncthreads();

        // store partial agg (deterministic), re-zero for next tile (same threads)
        if (tid < 128) {
            g_aggp[(size_t)t * F_ + tid] = S.agg[tid];
            S.agg[tid] = 0.f;
        }
    }
}

// ---------------- dense_out kernel: 8 rows/block, 4-way k-split, 512 thr ----------------
__global__ __launch_bounds__(512)
void out_kernel(const float* __restrict__ features,
                const float* __restrict__ Wo1, const float* __restrict__ bo1,
                const float* __restrict__ Wo2, const float* __restrict__ bo2,
                float* __restrict__ out) {
    __shared__ float agg[8][128];
    __shared__ float o1[8][128];
    __shared__ float part[4][8][128];
    const int tid = threadIdx.x;
    const int h   = tid & 127;
    const int q   = tid >> 7;          // 0..3
    const int bi0 = blockIdx.x * 8;

    for (int idx = tid; idx < 8 * 128; idx += 512) {
        int r = idx >> 7, c = idx & 127;
        agg[r][c] = g_aggp[(size_t)(2 * (bi0 + r))     * F_ + c]
                  + g_aggp[(size_t)(2 * (bi0 + r) + 1) * F_ + c];
    }
    __syncthreads();

    // phase 1: partial GEMV over f in [32q, 32q+32)
    {
        float acc[8];
#pragma unroll
        for (int r = 0; r < 8; r++) acc[r] = 0.f;
        const int f0 = 32 * q;
#pragma unroll 8
        for (int f = f0; f < f0 + 32; f++) {
            float wv = Wo1[f * H_ + h];
#pragma unroll
            for (int r = 0; r < 8; r++) acc[r] = fmaf(agg[r][f], wv, acc[r]);
        }
#pragma unroll
        for (int r = 0; r < 8; r++) part[q][r][h] = acc[r];
    }
    __syncthreads();
    {
        const float bv = bo1[h];
#pragma unroll
        for (int rr = 0; rr < 2; rr++) {
            int r = 2 * q + rr;
            float s = bv + part[0][r][h] + part[1][r][h] + part[2][r][h] + part[3][r][h];
            o1[r][h] = softplus_f(s);
        }
    }
    __syncthreads();

    // phase 2: partial GEMV over hp in [32q, 32q+32)
    {
        float acc[8];
#pragma unroll
        for (int r = 0; r < 8; r++) acc[r] = 0.f;
        const int h0 = 32 * q;
#pragma unroll 8
        for (int hp = h0; hp < h0 + 32; hp++) {
            float wv = Wo2[hp * H_ + h];
#pragma unroll
            for (int r = 0; r < 8; r++) acc[r] = fmaf(o1[r][hp], wv, acc[r]);
        }
#pragma unroll
        for (int r = 0; r < 8; r++) part[q][r][h] = acc[r];
    }
    __syncthreads();
    {
        const float bv = bo2[h];
#pragma unroll
        for (int rr = 0; rr < 2; rr++) {
            int r = 2 * q + rr;
            float s = bv + features[(size_t)(bi0 + r) * H_ + h]
                    + part[0][r][h] + part[1][r][h] + part[2][r][h] + part[3][r][h];
            out[(size_t)(bi0 + r) * H_ + h] = s;
        }
    }
}

// ---------------------------------------------------------------------------
extern "C" void kernel_launch(void* const* d_in, const int* in_sizes, int n_in,
                              void* d_out, int out_size) {
    const float* features = (const float*)d_in[0];
    const float* rbf      = (const float*)d_in[1];
    const int*   mask     = (const int*)  d_in[2];
    const float* W_rbf1   = (const float*)d_in[3];
    const float* b_rbf1   = (const float*)d_in[4];
    const float* W_rbf2   = (const float*)d_in[5];
    const float* b_rbf2   = (const float*)d_in[6];
    const float* W_f      = (const float*)d_in[7];
    const float* b_f      = (const float*)d_in[8];
    const float* W_o1     = (const float*)d_in[9];
    const float* b_o1     = (const float*)d_in[10];
    const float* W_o2     = (const float*)d_in[11];
    const float* b_o2     = (const float*)d_in[12];
    float* out = (float*)d_out;

    cudaFuncSetAttribute(main_kernel,
                         cudaFuncAttributeMaxDynamicSharedMemorySize,
                         (int)sizeof(SmemT));

    prep_weights<<<32, 256>>>(W_rbf1, W_rbf2);
    nf_kernel<<<BN_ / 8, 512>>>(features, W_f, b_f);
    main_kernel<<<GRID_MAIN, 256, sizeof(SmemT)>>>(rbf, mask, b_rbf1, b_rbf2);
    out_kernel<<<BN_ / 8, 512>>>(features, W_o1, b_o1, W_o2, b_o2, out);
}